// round 1
// baseline (speedup 1.0000x reference)
#include <cuda_runtime.h>
#include <math.h>

// Problem constants
#define Bc 2
#define Hn 16
#define Tn 2048
#define Dn 1024
#define DH 64
#define MT (Bc * Tn)   // 4096 rows

// Scratch (device globals; no cudaMalloc allowed)
__device__ float g_q[Bc * Hn * Tn * DH];
__device__ float g_k[Bc * Hn * Tn * DH];
__device__ float g_v[Bc * Hn * Tn * DH];
__device__ float g_att[Bc * Tn * Dn];
__device__ float g_cos[Tn * (DH / 2)];
__device__ float g_sin[Tn * (DH / 2)];

// ---------------------------------------------------------------------------
// RoPE cos/sin table. Angle computed in fp32 (matching reference rounding),
// trig in fp64 so accuracy is independent of fast-math flags.
// ---------------------------------------------------------------------------
__global__ void rope_table_kernel() {
    int idx = blockIdx.x * blockDim.x + threadIdx.x;
    if (idx >= Tn * (DH / 2)) return;
    int t = idx / (DH / 2);
    int i = idx % (DH / 2);
    float freq = (float)(1.0 / pow(10000.0, (double)(2 * i) / (double)DH));
    float ang = (float)t * freq;
    g_cos[idx] = (float)cos((double)ang);
    g_sin[idx] = (float)sin((double)ang);
}

// ---------------------------------------------------------------------------
// NT GEMM: C[m][n] = sum_k A[m][k] * W[n][k].   M=4096, N=K=1024.
// 128x128 tile, BK=16, 256 threads, 8x8 per thread.
// MODE 0: flat store C[m*Dn+n]
// MODE 1: scatter to [B,H,T,dh] layout
// MODE 2: scatter + RoPE
// ---------------------------------------------------------------------------
template <int MODE>
__global__ void __launch_bounds__(256) gemm_nt(const float* __restrict__ A,
                                               const float* __restrict__ W,
                                               float* __restrict__ C) {
    __shared__ float As[16][128];
    __shared__ float Bs[16][128];

    const int tid = threadIdx.x;
    const int tx = tid & 15;
    const int ty = tid >> 4;
    const int m0 = blockIdx.y * 128;
    const int n0 = blockIdx.x * 128;

    float acc[8][8];
#pragma unroll
    for (int i = 0; i < 8; i++)
#pragma unroll
        for (int j = 0; j < 8; j++) acc[i][j] = 0.0f;

    for (int k0 = 0; k0 < Dn; k0 += 16) {
#pragma unroll
        for (int w = 0; w < 2; w++) {
            int vi = tid + w * 256;          // 0..511
            int row = vi >> 2;               // 0..127
            int kc = (vi & 3) * 4;           // 0,4,8,12
            float4 a4 = *(const float4*)&A[(size_t)(m0 + row) * Dn + k0 + kc];
            As[kc + 0][row] = a4.x;
            As[kc + 1][row] = a4.y;
            As[kc + 2][row] = a4.z;
            As[kc + 3][row] = a4.w;
            float4 b4 = *(const float4*)&W[(size_t)(n0 + row) * Dn + k0 + kc];
            Bs[kc + 0][row] = b4.x;
            Bs[kc + 1][row] = b4.y;
            Bs[kc + 2][row] = b4.z;
            Bs[kc + 3][row] = b4.w;
        }
        __syncthreads();

#pragma unroll
        for (int kk = 0; kk < 16; kk++) {
            float a[8], b[8];
            *(float4*)&a[0] = *(const float4*)&As[kk][ty * 8];
            *(float4*)&a[4] = *(const float4*)&As[kk][ty * 8 + 4];
            *(float4*)&b[0] = *(const float4*)&Bs[kk][tx * 8];
            *(float4*)&b[4] = *(const float4*)&Bs[kk][tx * 8 + 4];
#pragma unroll
            for (int i = 0; i < 8; i++)
#pragma unroll
                for (int j = 0; j < 8; j++) acc[i][j] += a[i] * b[j];
        }
        __syncthreads();
    }

    // Epilogue
    if (MODE == 0) {
#pragma unroll
        for (int i = 0; i < 8; i++) {
            int m = m0 + ty * 8 + i;
#pragma unroll
            for (int j = 0; j < 8; j += 4) {
                int n = n0 + tx * 8 + j;
                float4 v4 = make_float4(acc[i][j], acc[i][j + 1], acc[i][j + 2], acc[i][j + 3]);
                *(float4*)&C[(size_t)m * Dn + n] = v4;
            }
        }
    } else {
#pragma unroll
        for (int i = 0; i < 8; i++) {
            int m = m0 + ty * 8 + i;
            int b = m >> 11;           // /2048
            int t = m & 2047;
            if (MODE == 2) {
#pragma unroll
                for (int j = 0; j < 8; j += 2) {
                    int n = n0 + tx * 8 + j;
                    int h = n >> 6;
                    int d = n & 63;
                    int ip = d >> 1;
                    float c = g_cos[t * (DH / 2) + ip];
                    float s = g_sin[t * (DH / 2) + ip];
                    float re = acc[i][j], im = acc[i][j + 1];
                    float* out = &C[(((size_t)(b * Hn + h)) * Tn + t) * DH + d];
                    out[0] = re * c - im * s;
                    out[1] = re * s + im * c;
                }
            } else {
#pragma unroll
                for (int j = 0; j < 8; j += 4) {
                    int n = n0 + tx * 8 + j;
                    int h = n >> 6;
                    int d = n & 63;
                    float4 v4 = make_float4(acc[i][j], acc[i][j + 1], acc[i][j + 2], acc[i][j + 3]);
                    *(float4*)&C[(((size_t)(b * Hn + h)) * Tn + t) * DH + d] = v4;
                }
            }
        }
    }
}

// ---------------------------------------------------------------------------
// Flash attention, causal, fp32. BQ=BKV=64, dh=64.
// 256 threads in 16x16 grid; each thread 4 S-rows x 4 S-cols and 4x4 of O.
// P is written over the K smem buffer.
// ---------------------------------------------------------------------------
#define PAD 68
#define ATTN_SMEM (3 * 64 * PAD * 4)

__global__ void __launch_bounds__(256) attn_kernel(float* __restrict__ Oatt) {
    extern __shared__ float sm[];
    float* q_s  = sm;
    float* kp_s = sm + 64 * PAD;
    float* v_s  = sm + 2 * 64 * PAD;

    const int tid = threadIdx.x;
    const int tx = tid & 15;
    const int ty = tid >> 4;
    const int tx4 = tx * 4;
    const int ty4 = ty * 4;
    const int qt = blockIdx.x;
    const int h = blockIdx.y;
    const int b = blockIdx.z;
    const int q0 = qt * 64;

    const float* Qb = g_q + ((size_t)(b * Hn + h)) * Tn * DH;
    const float* Kb = g_k + ((size_t)(b * Hn + h)) * Tn * DH;
    const float* Vb = g_v + ((size_t)(b * Hn + h)) * Tn * DH;

    // load Q tile
#pragma unroll
    for (int w = 0; w < 4; w++) {
        int vi = tid + w * 256;      // 0..1023
        int row = vi >> 4;
        int c4 = (vi & 15) * 4;
        *(float4*)&q_s[row * PAD + c4] = *(const float4*)&Qb[(size_t)(q0 + row) * DH + c4];
    }

    float m_i[4], l_i[4], o[4][4];
#pragma unroll
    for (int i = 0; i < 4; i++) {
        m_i[i] = -1.0e30f;
        l_i[i] = 0.0f;
#pragma unroll
        for (int j = 0; j < 4; j++) o[i][j] = 0.0f;
    }

    for (int jt = 0; jt <= qt; jt++) {
        const int k0 = jt * 64;
        __syncthreads();
#pragma unroll
        for (int w = 0; w < 4; w++) {
            int vi = tid + w * 256;
            int row = vi >> 4;
            int c4 = (vi & 15) * 4;
            *(float4*)&kp_s[row * PAD + c4] = *(const float4*)&Kb[(size_t)(k0 + row) * DH + c4];
            *(float4*)&v_s[row * PAD + c4]  = *(const float4*)&Vb[(size_t)(k0 + row) * DH + c4];
        }
        __syncthreads();

        // S = Q @ K^T (64x64)
        float s[4][4] = {};
#pragma unroll 4
        for (int d4 = 0; d4 < 64; d4 += 4) {
            float4 qa[4], kb[4];
#pragma unroll
            for (int i = 0; i < 4; i++) qa[i] = *(const float4*)&q_s[(ty4 + i) * PAD + d4];
#pragma unroll
            for (int j = 0; j < 4; j++) kb[j] = *(const float4*)&kp_s[(tx4 + j) * PAD + d4];
#pragma unroll
            for (int i = 0; i < 4; i++)
#pragma unroll
                for (int j = 0; j < 4; j++)
                    s[i][j] += qa[i].x * kb[j].x + qa[i].y * kb[j].y +
                               qa[i].z * kb[j].z + qa[i].w * kb[j].w;
        }

        // scale + causal mask
        const bool diag = (jt == qt);
#pragma unroll
        for (int i = 0; i < 4; i++)
#pragma unroll
            for (int j = 0; j < 4; j++) {
                float v = s[i][j] * 0.125f;
                if (diag && (k0 + tx4 + j) > (q0 + ty4 + i)) v = -3.0e38f;
                s[i][j] = v;
            }

        // online softmax (row stats across the 16-thread tx group)
#pragma unroll
        for (int i = 0; i < 4; i++) {
            float mx = fmaxf(fmaxf(s[i][0], s[i][1]), fmaxf(s[i][2], s[i][3]));
#pragma unroll
            for (int off = 8; off > 0; off >>= 1)
                mx = fmaxf(mx, __shfl_xor_sync(0xffffffffu, mx, off));
            float mnew = fmaxf(m_i[i], mx);
            float alpha = __expf(m_i[i] - mnew);
            m_i[i] = mnew;
            float rs = 0.0f;
#pragma unroll
            for (int j = 0; j < 4; j++) {
                float p = __expf(s[i][j] - mnew);
                s[i][j] = p;
                rs += p;
            }
#pragma unroll
            for (int off = 8; off > 0; off >>= 1)
                rs += __shfl_xor_sync(0xffffffffu, rs, off);
            l_i[i] = l_i[i] * alpha + rs;
#pragma unroll
            for (int j = 0; j < 4; j++) o[i][j] *= alpha;
        }

        __syncthreads();   // everyone done reading K from kp_s
#pragma unroll
        for (int i = 0; i < 4; i++)
#pragma unroll
            for (int j = 0; j < 4; j++) kp_s[(ty4 + i) * PAD + tx4 + j] = s[i][j];
        __syncthreads();

        // O += P @ V
#pragma unroll 4
        for (int kk = 0; kk < 64; kk += 4) {
            float4 pa[4], vb[4];
#pragma unroll
            for (int i = 0; i < 4; i++) pa[i] = *(const float4*)&kp_s[(ty4 + i) * PAD + kk];
#pragma unroll
            for (int u = 0; u < 4; u++) vb[u] = *(const float4*)&v_s[(kk + u) * PAD + tx4];
#pragma unroll
            for (int i = 0; i < 4; i++) {
                o[i][0] += pa[i].x * vb[0].x + pa[i].y * vb[1].x + pa[i].z * vb[2].x + pa[i].w * vb[3].x;
                o[i][1] += pa[i].x * vb[0].y + pa[i].y * vb[1].y + pa[i].z * vb[2].y + pa[i].w * vb[3].y;
                o[i][2] += pa[i].x * vb[0].z + pa[i].y * vb[1].z + pa[i].z * vb[2].z + pa[i].w * vb[3].z;
                o[i][3] += pa[i].x * vb[0].w + pa[i].y * vb[1].w + pa[i].z * vb[2].w + pa[i].w * vb[3].w;
            }
        }
    }

    // epilogue: O / l, store to [B, T, D] with D = H*dh
#pragma unroll
    for (int i = 0; i < 4; i++) {
        float inv = 1.0f / l_i[i];
        float4 ov = make_float4(o[i][0] * inv, o[i][1] * inv, o[i][2] * inv, o[i][3] * inv);
        *(float4*)&Oatt[((size_t)b * Tn + (q0 + ty4 + i)) * Dn + h * DH + tx4] = ov;
    }
}

// ---------------------------------------------------------------------------
// launch
// ---------------------------------------------------------------------------
extern "C" void kernel_launch(void* const* d_in, const int* in_sizes, int n_in,
                              void* d_out, int out_size) {
    const float* x  = (const float*)d_in[0];
    const float* wq = (const float*)d_in[1];
    const float* wk = (const float*)d_in[2];
    const float* wv = (const float*)d_in[3];
    const float* wo = (const float*)d_in[4];
    float* out = (float*)d_out;

    float *pq, *pk, *pv, *patt;
    cudaGetSymbolAddress((void**)&pq, g_q);
    cudaGetSymbolAddress((void**)&pk, g_k);
    cudaGetSymbolAddress((void**)&pv, g_v);
    cudaGetSymbolAddress((void**)&patt, g_att);

    // rope tables
    rope_table_kernel<<<(Tn * (DH / 2) + 255) / 256, 256>>>();

    // projections (+ RoPE fused for q, k)
    dim3 gg(Dn / 128, MT / 128);
    gemm_nt<2><<<gg, 256>>>(x, wq, pq);
    gemm_nt<2><<<gg, 256>>>(x, wk, pk);
    gemm_nt<1><<<gg, 256>>>(x, wv, pv);

    // attention
    cudaFuncSetAttribute(attn_kernel, cudaFuncAttributeMaxDynamicSharedMemorySize, ATTN_SMEM);
    attn_kernel<<<dim3(Tn / 64, Hn, Bc), 256, ATTN_SMEM>>>(patt);

    // output projection
    gemm_nt<0><<<gg, 256>>>(patt, wo, out);
}

// round 3
// speedup vs baseline: 1.3667x; 1.3667x over previous
#include <cuda_runtime.h>
#include <cuda_bf16.h>
#include <cstdint>
#include <math.h>

// Problem constants
#define Bc 2
#define Hn 16
#define Tn 2048
#define Dn 1024
#define DH 64
#define MT (Bc * Tn)   // 4096 rows

// Scratch (device globals; no cudaMalloc allowed)
__device__ float g_q[Bc * Hn * Tn * DH];
__device__ float g_k[Bc * Hn * Tn * DH];
__device__ float g_v[Bc * Hn * Tn * DH];
__device__ float g_att[Bc * Tn * Dn];
__device__ float g_cos[Tn * (DH / 2)];
__device__ float g_sin[Tn * (DH / 2)];

// ---------------------------------------------------------------------------
// RoPE cos/sin table (fp64 trig on fp32-rounded angle; fast-math-proof)
// ---------------------------------------------------------------------------
__global__ void rope_table_kernel() {
    int idx = blockIdx.x * blockDim.x + threadIdx.x;
    if (idx >= Tn * (DH / 2)) return;
    int t = idx / (DH / 2);
    int i = idx % (DH / 2);
    float freq = (float)(1.0 / pow(10000.0, (double)(2 * i) / (double)DH));
    float ang = (float)t * freq;
    g_cos[idx] = (float)cos((double)ang);
    g_sin[idx] = (float)sin((double)ang);
}

// ---------------------------------------------------------------------------
// Tensor-core NT GEMM with bf16x3 fp32 emulation.
// C[m][n] = sum_k A[m][k] * W[n][k].  M=4096, N=K=1024.
// Block tile 128x128, BK=32, 8 warps; warp tile 64x32 (4x4 m16n8k16 atoms).
// MODE 0: flat store. MODE 1: scatter to [B,H,T,dh]. MODE 2: scatter + RoPE.
// ---------------------------------------------------------------------------
#define LDK 40   // smem row stride in bf16 (80B: 16B-aligned, ldmatrix conflict-free)

__device__ __forceinline__ void mma_bf16(float* c, const unsigned* a,
                                         unsigned b0, unsigned b1) {
    asm volatile(
        "mma.sync.aligned.m16n8k16.row.col.f32.bf16.bf16.f32 "
        "{%0,%1,%2,%3}, {%4,%5,%6,%7}, {%8,%9}, {%0,%1,%2,%3};\n"
        : "+f"(c[0]), "+f"(c[1]), "+f"(c[2]), "+f"(c[3])
        : "r"(a[0]), "r"(a[1]), "r"(a[2]), "r"(a[3]), "r"(b0), "r"(b1));
}

__device__ __forceinline__ void ldsm4(unsigned* r, unsigned addr) {
    asm volatile("ldmatrix.sync.aligned.m8n8.x4.shared.b16 {%0,%1,%2,%3}, [%4];\n"
                 : "=r"(r[0]), "=r"(r[1]), "=r"(r[2]), "=r"(r[3]) : "r"(addr));
}

// split fp32 pair into (hi, lo) bf16x2 and store to smem
__device__ __forceinline__ void split_store(float v0, float v1,
                                            __nv_bfloat16* hp, __nv_bfloat16* lp) {
    __nv_bfloat162 hh, ll;
    hh.x = __float2bfloat16(v0);
    hh.y = __float2bfloat16(v1);
    ll.x = __float2bfloat16(v0 - __bfloat162float(hh.x));
    ll.y = __float2bfloat16(v1 - __bfloat162float(hh.y));
    *(__nv_bfloat162*)hp = hh;
    *(__nv_bfloat162*)lp = ll;
}

template <int MODE>
__global__ void __launch_bounds__(256) gemm_tc(const float* __restrict__ A,
                                               const float* __restrict__ W,
                                               float* __restrict__ C) {
    __shared__ __align__(16) __nv_bfloat16 Ah_s[128 * LDK];
    __shared__ __align__(16) __nv_bfloat16 Al_s[128 * LDK];
    __shared__ __align__(16) __nv_bfloat16 Bh_s[128 * LDK];
    __shared__ __align__(16) __nv_bfloat16 Bl_s[128 * LDK];

    const int tid = threadIdx.x;
    const int warp = tid >> 5;
    const int lane = tid & 31;
    const int m0 = blockIdx.y * 128;
    const int n0 = blockIdx.x * 128;
    const int wm = warp >> 2;   // 0..1
    const int wn = warp & 3;    // 0..3

    const unsigned ah_base = (unsigned)__cvta_generic_to_shared(Ah_s);
    const unsigned al_base = (unsigned)__cvta_generic_to_shared(Al_s);
    const unsigned bh_base = (unsigned)__cvta_generic_to_shared(Bh_s);
    const unsigned bl_base = (unsigned)__cvta_generic_to_shared(Bl_s);

    float acc[4][4][4];
#pragma unroll
    for (int i = 0; i < 4; i++)
#pragma unroll
        for (int j = 0; j < 4; j++)
#pragma unroll
            for (int r = 0; r < 4; r++) acc[i][j][r] = 0.0f;

    float4 ra[4], rb[4];

    // prologue: load k-tile 0
#pragma unroll
    for (int w = 0; w < 4; w++) {
        int idx = tid + w * 256;
        int row = idx >> 3, c = (idx & 7) * 4;
        ra[w] = *(const float4*)&A[(size_t)(m0 + row) * Dn + c];
        rb[w] = *(const float4*)&W[(size_t)(n0 + row) * Dn + c];
    }
#pragma unroll
    for (int w = 0; w < 4; w++) {
        int idx = tid + w * 256;
        int row = idx >> 3, c = (idx & 7) * 4;
        split_store(ra[w].x, ra[w].y, &Ah_s[row * LDK + c],     &Al_s[row * LDK + c]);
        split_store(ra[w].z, ra[w].w, &Ah_s[row * LDK + c + 2], &Al_s[row * LDK + c + 2]);
        split_store(rb[w].x, rb[w].y, &Bh_s[row * LDK + c],     &Bl_s[row * LDK + c]);
        split_store(rb[w].z, rb[w].w, &Bh_s[row * LDK + c + 2], &Bl_s[row * LDK + c + 2]);
    }
    __syncthreads();

    for (int k0 = 0; k0 < Dn; k0 += 32) {
        const bool more = (k0 + 32 < Dn);
        if (more) {
#pragma unroll
            for (int w = 0; w < 4; w++) {
                int idx = tid + w * 256;
                int row = idx >> 3, c = (idx & 7) * 4;
                ra[w] = *(const float4*)&A[(size_t)(m0 + row) * Dn + k0 + 32 + c];
                rb[w] = *(const float4*)&W[(size_t)(n0 + row) * Dn + k0 + 32 + c];
            }
        }

        // compute both k16 substeps from smem
#pragma unroll
        for (int s = 0; s < 2; s++) {
            const int ks = s * 16;
            unsigned ah[4][4], al[4][4], bh[2][4], bl[2][4];
            const int ar = wm * 64 + (lane & 7) + ((lane >> 3) & 1) * 8;
            const int ac = ks + (lane >> 4) * 8;
#pragma unroll
            for (int ma = 0; ma < 4; ma++) {
                unsigned off = (unsigned)(((ar + ma * 16) * LDK + ac) * 2);
                ldsm4(ah[ma], ah_base + off);
                ldsm4(al[ma], al_base + off);
            }
            const int br = wn * 32 + (lane & 7) + (lane >> 4) * 8;
            const int bc = ks + ((lane >> 3) & 1) * 8;
#pragma unroll
            for (int nb = 0; nb < 2; nb++) {
                unsigned off = (unsigned)(((br + nb * 16) * LDK + bc) * 2);
                ldsm4(bh[nb], bh_base + off);
                ldsm4(bl[nb], bl_base + off);
            }
#pragma unroll
            for (int ma = 0; ma < 4; ma++)
#pragma unroll
                for (int na = 0; na < 4; na++) {
                    const int nb = na >> 1, pr = (na & 1) * 2;
                    mma_bf16(acc[ma][na], ah[ma], bh[nb][pr], bh[nb][pr + 1]);
                    mma_bf16(acc[ma][na], ah[ma], bl[nb][pr], bl[nb][pr + 1]);
                    mma_bf16(acc[ma][na], al[ma], bh[nb][pr], bh[nb][pr + 1]);
                }
        }
        __syncthreads();

        if (more) {
#pragma unroll
            for (int w = 0; w < 4; w++) {
                int idx = tid + w * 256;
                int row = idx >> 3, c = (idx & 7) * 4;
                split_store(ra[w].x, ra[w].y, &Ah_s[row * LDK + c],     &Al_s[row * LDK + c]);
                split_store(ra[w].z, ra[w].w, &Ah_s[row * LDK + c + 2], &Al_s[row * LDK + c + 2]);
                split_store(rb[w].x, rb[w].y, &Bh_s[row * LDK + c],     &Bl_s[row * LDK + c]);
                split_store(rb[w].z, rb[w].w, &Bh_s[row * LDK + c + 2], &Bl_s[row * LDK + c + 2]);
            }
            __syncthreads();
        }
    }

    // epilogue: fragment (c0,c1) = (row tg, cols 2ti/2ti+1), (c2,c3) = row tg+8
    const int tg = lane >> 2;
    const int ti = lane & 3;
#pragma unroll
    for (int ma = 0; ma < 4; ma++) {
#pragma unroll
        for (int na = 0; na < 4; na++) {
#pragma unroll
            for (int rr = 0; rr < 2; rr++) {
                int m = m0 + wm * 64 + ma * 16 + tg + rr * 8;
                int n = n0 + wn * 32 + na * 8 + 2 * ti;
                float c0 = acc[ma][na][rr * 2 + 0];
                float c1 = acc[ma][na][rr * 2 + 1];
                if (MODE == 0) {
                    float2 v2 = make_float2(c0, c1);
                    *(float2*)&C[(size_t)m * Dn + n] = v2;
                } else {
                    int b = m >> 11;
                    int t = m & 2047;
                    int h = n >> 6;
                    int d = n & 63;
                    float* outp = &C[(((size_t)(b * Hn + h)) * Tn + t) * DH + d];
                    if (MODE == 2) {
                        float cc = g_cos[t * (DH / 2) + (d >> 1)];
                        float ss = g_sin[t * (DH / 2) + (d >> 1)];
                        outp[0] = c0 * cc - c1 * ss;
                        outp[1] = c0 * ss + c1 * cc;
                    } else {
                        float2 v2 = make_float2(c0, c1);
                        *(float2*)outp = v2;
                    }
                }
            }
        }
    }
}

// ---------------------------------------------------------------------------
// Flash attention, causal, fp32 (unchanged from R1). BQ=BKV=64, dh=64.
// ---------------------------------------------------------------------------
#define PAD 68
#define ATTN_SMEM (3 * 64 * PAD * 4)

__global__ void __launch_bounds__(256) attn_kernel(float* __restrict__ Oatt) {
    extern __shared__ float sm[];
    float* q_s  = sm;
    float* kp_s = sm + 64 * PAD;
    float* v_s  = sm + 2 * 64 * PAD;

    const int tid = threadIdx.x;
    const int tx = tid & 15;
    const int ty = tid >> 4;
    const int tx4 = tx * 4;
    const int ty4 = ty * 4;
    const int qt = blockIdx.x;
    const int h = blockIdx.y;
    const int b = blockIdx.z;
    const int q0 = qt * 64;

    const float* Qb = g_q + ((size_t)(b * Hn + h)) * Tn * DH;
    const float* Kb = g_k + ((size_t)(b * Hn + h)) * Tn * DH;
    const float* Vb = g_v + ((size_t)(b * Hn + h)) * Tn * DH;

#pragma unroll
    for (int w = 0; w < 4; w++) {
        int vi = tid + w * 256;
        int row = vi >> 4;
        int c4 = (vi & 15) * 4;
        *(float4*)&q_s[row * PAD + c4] = *(const float4*)&Qb[(size_t)(q0 + row) * DH + c4];
    }

    float m_i[4], l_i[4], o[4][4];
#pragma unroll
    for (int i = 0; i < 4; i++) {
        m_i[i] = -1.0e30f;
        l_i[i] = 0.0f;
#pragma unroll
        for (int j = 0; j < 4; j++) o[i][j] = 0.0f;
    }

    for (int jt = 0; jt <= qt; jt++) {
        const int k0 = jt * 64;
        __syncthreads();
#pragma unroll
        for (int w = 0; w < 4; w++) {
            int vi = tid + w * 256;
            int row = vi >> 4;
            int c4 = (vi & 15) * 4;
            *(float4*)&kp_s[row * PAD + c4] = *(const float4*)&Kb[(size_t)(k0 + row) * DH + c4];
            *(float4*)&v_s[row * PAD + c4]  = *(const float4*)&Vb[(size_t)(k0 + row) * DH + c4];
        }
        __syncthreads();

        float s[4][4] = {};
#pragma unroll 4
        for (int d4 = 0; d4 < 64; d4 += 4) {
            float4 qa[4], kb[4];
#pragma unroll
            for (int i = 0; i < 4; i++) qa[i] = *(const float4*)&q_s[(ty4 + i) * PAD + d4];
#pragma unroll
            for (int j = 0; j < 4; j++) kb[j] = *(const float4*)&kp_s[(tx4 + j) * PAD + d4];
#pragma unroll
            for (int i = 0; i < 4; i++)
#pragma unroll
                for (int j = 0; j < 4; j++)
                    s[i][j] += qa[i].x * kb[j].x + qa[i].y * kb[j].y +
                               qa[i].z * kb[j].z + qa[i].w * kb[j].w;
        }

        const bool diag = (jt == qt);
#pragma unroll
        for (int i = 0; i < 4; i++)
#pragma unroll
            for (int j = 0; j < 4; j++) {
                float v = s[i][j] * 0.125f;
                if (diag && (k0 + tx4 + j) > (q0 + ty4 + i)) v = -3.0e38f;
                s[i][j] = v;
            }

#pragma unroll
        for (int i = 0; i < 4; i++) {
            float mx = fmaxf(fmaxf(s[i][0], s[i][1]), fmaxf(s[i][2], s[i][3]));
#pragma unroll
            for (int off = 8; off > 0; off >>= 1)
                mx = fmaxf(mx, __shfl_xor_sync(0xffffffffu, mx, off));
            float mnew = fmaxf(m_i[i], mx);
            float alpha = __expf(m_i[i] - mnew);
            m_i[i] = mnew;
            float rs = 0.0f;
#pragma unroll
            for (int j = 0; j < 4; j++) {
                float p = __expf(s[i][j] - mnew);
                s[i][j] = p;
                rs += p;
            }
#pragma unroll
            for (int off = 8; off > 0; off >>= 1)
                rs += __shfl_xor_sync(0xffffffffu, rs, off);
            l_i[i] = l_i[i] * alpha + rs;
#pragma unroll
            for (int j = 0; j < 4; j++) o[i][j] *= alpha;
        }

        __syncthreads();
#pragma unroll
        for (int i = 0; i < 4; i++)
#pragma unroll
            for (int j = 0; j < 4; j++) kp_s[(ty4 + i) * PAD + tx4 + j] = s[i][j];
        __syncthreads();

#pragma unroll 4
        for (int kk = 0; kk < 64; kk += 4) {
            float4 pa[4], vb[4];
#pragma unroll
            for (int i = 0; i < 4; i++) pa[i] = *(const float4*)&kp_s[(ty4 + i) * PAD + kk];
#pragma unroll
            for (int u = 0; u < 4; u++) vb[u] = *(const float4*)&v_s[(kk + u) * PAD + tx4];
#pragma unroll
            for (int i = 0; i < 4; i++) {
                o[i][0] += pa[i].x * vb[0].x + pa[i].y * vb[1].x + pa[i].z * vb[2].x + pa[i].w * vb[3].x;
                o[i][1] += pa[i].x * vb[0].y + pa[i].y * vb[1].y + pa[i].z * vb[2].y + pa[i].w * vb[3].y;
                o[i][2] += pa[i].x * vb[0].z + pa[i].y * vb[1].z + pa[i].z * vb[2].z + pa[i].w * vb[3].z;
                o[i][3] += pa[i].x * vb[0].w + pa[i].y * vb[1].w + pa[i].z * vb[2].w + pa[i].w * vb[3].w;
            }
        }
    }

#pragma unroll
    for (int i = 0; i < 4; i++) {
        float inv = 1.0f / l_i[i];
        float4 ov = make_float4(o[i][0] * inv, o[i][1] * inv, o[i][2] * inv, o[i][3] * inv);
        *(float4*)&Oatt[((size_t)b * Tn + (q0 + ty4 + i)) * Dn + h * DH + tx4] = ov;
    }
}

// ---------------------------------------------------------------------------
// launch
// ---------------------------------------------------------------------------
extern "C" void kernel_launch(void* const* d_in, const int* in_sizes, int n_in,
                              void* d_out, int out_size) {
    const float* x  = (const float*)d_in[0];
    const float* wq = (const float*)d_in[1];
    const float* wk = (const float*)d_in[2];
    const float* wv = (const float*)d_in[3];
    const float* wo = (const float*)d_in[4];
    float* out = (float*)d_out;

    float *pq, *pk, *pv, *patt;
    cudaGetSymbolAddress((void**)&pq, g_q);
    cudaGetSymbolAddress((void**)&pk, g_k);
    cudaGetSymbolAddress((void**)&pv, g_v);
    cudaGetSymbolAddress((void**)&patt, g_att);

    rope_table_kernel<<<(Tn * (DH / 2) + 255) / 256, 256>>>();

    dim3 gg(Dn / 128, MT / 128);
    gemm_tc<2><<<gg, 256>>>(x, wq, pq);
    gemm_tc<2><<<gg, 256>>>(x, wk, pk);
    gemm_tc<1><<<gg, 256>>>(x, wv, pv);

    cudaFuncSetAttribute(attn_kernel, cudaFuncAttributeMaxDynamicSharedMemorySize, ATTN_SMEM);
    attn_kernel<<<dim3(Tn / 64, Hn, Bc), 256, ATTN_SMEM>>>(patt);

    gemm_tc<0><<<gg, 256>>>(patt, wo, out);
}

// round 4
// speedup vs baseline: 2.9491x; 2.1579x over previous
#include <cuda_runtime.h>
#include <cuda_bf16.h>
#include <cstdint>
#include <math.h>

// Problem constants
#define Bc 2
#define Hn 16
#define Tn 2048
#define Dn 1024
#define DH 64
#define MT (Bc * Tn)   // 4096 rows

// Scratch (device globals; no cudaMalloc allowed)
__device__ float g_q[Bc * Hn * Tn * DH];
__device__ float g_k[Bc * Hn * Tn * DH];
__device__ float g_v[Bc * Hn * Tn * DH];
__device__ float g_att[Bc * Tn * Dn];
__device__ float g_cos[Tn * (DH / 2)];
__device__ float g_sin[Tn * (DH / 2)];

// ---------------------------------------------------------------------------
// RoPE cos/sin table (fp64 trig on fp32-rounded angle; fast-math-proof)
// ---------------------------------------------------------------------------
__global__ void rope_table_kernel() {
    int idx = blockIdx.x * blockDim.x + threadIdx.x;
    if (idx >= Tn * (DH / 2)) return;
    int t = idx / (DH / 2);
    int i = idx % (DH / 2);
    float freq = (float)(1.0 / pow(10000.0, (double)(2 * i) / (double)DH));
    float ang = (float)t * freq;
    g_cos[idx] = (float)cos((double)ang);
    g_sin[idx] = (float)sin((double)ang);
}

// ---------------------------------------------------------------------------
// Shared MMA helpers
// ---------------------------------------------------------------------------
__device__ __forceinline__ void mma_bf16(float* c, const unsigned* a,
                                         unsigned b0, unsigned b1) {
    asm volatile(
        "mma.sync.aligned.m16n8k16.row.col.f32.bf16.bf16.f32 "
        "{%0,%1,%2,%3}, {%4,%5,%6,%7}, {%8,%9}, {%0,%1,%2,%3};\n"
        : "+f"(c[0]), "+f"(c[1]), "+f"(c[2]), "+f"(c[3])
        : "r"(a[0]), "r"(a[1]), "r"(a[2]), "r"(a[3]), "r"(b0), "r"(b1));
}

__device__ __forceinline__ void ldsm4(unsigned* r, unsigned addr) {
    asm volatile("ldmatrix.sync.aligned.m8n8.x4.shared.b16 {%0,%1,%2,%3}, [%4];\n"
                 : "=r"(r[0]), "=r"(r[1]), "=r"(r[2]), "=r"(r[3]) : "r"(addr));
}

__device__ __forceinline__ void ldsm4t(unsigned* r, unsigned addr) {
    asm volatile("ldmatrix.sync.aligned.m8n8.x4.trans.shared.b16 {%0,%1,%2,%3}, [%4];\n"
                 : "=r"(r[0]), "=r"(r[1]), "=r"(r[2]), "=r"(r[3]) : "r"(addr));
}

// split fp32 pair into (hi, lo) bf16x2 and store to smem
__device__ __forceinline__ void split_store(float v0, float v1,
                                            __nv_bfloat16* hp, __nv_bfloat16* lp) {
    __nv_bfloat162 hh, ll;
    hh.x = __float2bfloat16(v0);
    hh.y = __float2bfloat16(v1);
    ll.x = __float2bfloat16(v0 - __bfloat162float(hh.x));
    ll.y = __float2bfloat16(v1 - __bfloat162float(hh.y));
    *(__nv_bfloat162*)hp = hh;
    *(__nv_bfloat162*)lp = ll;
}

// split fp32 pair into packed hi / lo bf16x2 register values
__device__ __forceinline__ void split2(float x, float y, unsigned& h, unsigned& l) {
    __nv_bfloat162 hh, ll;
    hh.x = __float2bfloat16(x);
    hh.y = __float2bfloat16(y);
    ll.x = __float2bfloat16(x - __bfloat162float(hh.x));
    ll.y = __float2bfloat16(y - __bfloat162float(hh.y));
    h = *(unsigned*)&hh;
    l = *(unsigned*)&ll;
}

// ---------------------------------------------------------------------------
// Tensor-core NT GEMM with bf16x3 fp32 emulation (unchanged from R3).
// ---------------------------------------------------------------------------
#define LDK 40

template <int MODE>
__global__ void __launch_bounds__(256) gemm_tc(const float* __restrict__ A,
                                               const float* __restrict__ W,
                                               float* __restrict__ C) {
    __shared__ __align__(16) __nv_bfloat16 Ah_s[128 * LDK];
    __shared__ __align__(16) __nv_bfloat16 Al_s[128 * LDK];
    __shared__ __align__(16) __nv_bfloat16 Bh_s[128 * LDK];
    __shared__ __align__(16) __nv_bfloat16 Bl_s[128 * LDK];

    const int tid = threadIdx.x;
    const int warp = tid >> 5;
    const int lane = tid & 31;
    const int m0 = blockIdx.y * 128;
    const int n0 = blockIdx.x * 128;
    const int wm = warp >> 2;
    const int wn = warp & 3;

    const unsigned ah_base = (unsigned)__cvta_generic_to_shared(Ah_s);
    const unsigned al_base = (unsigned)__cvta_generic_to_shared(Al_s);
    const unsigned bh_base = (unsigned)__cvta_generic_to_shared(Bh_s);
    const unsigned bl_base = (unsigned)__cvta_generic_to_shared(Bl_s);

    float acc[4][4][4];
#pragma unroll
    for (int i = 0; i < 4; i++)
#pragma unroll
        for (int j = 0; j < 4; j++)
#pragma unroll
            for (int r = 0; r < 4; r++) acc[i][j][r] = 0.0f;

    float4 ra[4], rb[4];

#pragma unroll
    for (int w = 0; w < 4; w++) {
        int idx = tid + w * 256;
        int row = idx >> 3, c = (idx & 7) * 4;
        ra[w] = *(const float4*)&A[(size_t)(m0 + row) * Dn + c];
        rb[w] = *(const float4*)&W[(size_t)(n0 + row) * Dn + c];
    }
#pragma unroll
    for (int w = 0; w < 4; w++) {
        int idx = tid + w * 256;
        int row = idx >> 3, c = (idx & 7) * 4;
        split_store(ra[w].x, ra[w].y, &Ah_s[row * LDK + c],     &Al_s[row * LDK + c]);
        split_store(ra[w].z, ra[w].w, &Ah_s[row * LDK + c + 2], &Al_s[row * LDK + c + 2]);
        split_store(rb[w].x, rb[w].y, &Bh_s[row * LDK + c],     &Bl_s[row * LDK + c]);
        split_store(rb[w].z, rb[w].w, &Bh_s[row * LDK + c + 2], &Bl_s[row * LDK + c + 2]);
    }
    __syncthreads();

    for (int k0 = 0; k0 < Dn; k0 += 32) {
        const bool more = (k0 + 32 < Dn);
        if (more) {
#pragma unroll
            for (int w = 0; w < 4; w++) {
                int idx = tid + w * 256;
                int row = idx >> 3, c = (idx & 7) * 4;
                ra[w] = *(const float4*)&A[(size_t)(m0 + row) * Dn + k0 + 32 + c];
                rb[w] = *(const float4*)&W[(size_t)(n0 + row) * Dn + k0 + 32 + c];
            }
        }

#pragma unroll
        for (int s = 0; s < 2; s++) {
            const int ks = s * 16;
            unsigned ah[4][4], al[4][4], bh[2][4], bl[2][4];
            const int ar = wm * 64 + (lane & 7) + ((lane >> 3) & 1) * 8;
            const int ac = ks + (lane >> 4) * 8;
#pragma unroll
            for (int ma = 0; ma < 4; ma++) {
                unsigned off = (unsigned)(((ar + ma * 16) * LDK + ac) * 2);
                ldsm4(ah[ma], ah_base + off);
                ldsm4(al[ma], al_base + off);
            }
            const int br = wn * 32 + (lane & 7) + (lane >> 4) * 8;
            const int bc = ks + ((lane >> 3) & 1) * 8;
#pragma unroll
            for (int nb = 0; nb < 2; nb++) {
                unsigned off = (unsigned)(((br + nb * 16) * LDK + bc) * 2);
                ldsm4(bh[nb], bh_base + off);
                ldsm4(bl[nb], bl_base + off);
            }
#pragma unroll
            for (int ma = 0; ma < 4; ma++)
#pragma unroll
                for (int na = 0; na < 4; na++) {
                    const int nb = na >> 1, pr = (na & 1) * 2;
                    mma_bf16(acc[ma][na], ah[ma], bh[nb][pr], bh[nb][pr + 1]);
                    mma_bf16(acc[ma][na], ah[ma], bl[nb][pr], bl[nb][pr + 1]);
                    mma_bf16(acc[ma][na], al[ma], bh[nb][pr], bh[nb][pr + 1]);
                }
        }
        __syncthreads();

        if (more) {
#pragma unroll
            for (int w = 0; w < 4; w++) {
                int idx = tid + w * 256;
                int row = idx >> 3, c = (idx & 7) * 4;
                split_store(ra[w].x, ra[w].y, &Ah_s[row * LDK + c],     &Al_s[row * LDK + c]);
                split_store(ra[w].z, ra[w].w, &Ah_s[row * LDK + c + 2], &Al_s[row * LDK + c + 2]);
                split_store(rb[w].x, rb[w].y, &Bh_s[row * LDK + c],     &Bl_s[row * LDK + c]);
                split_store(rb[w].z, rb[w].w, &Bh_s[row * LDK + c + 2], &Bl_s[row * LDK + c + 2]);
            }
            __syncthreads();
        }
    }

    const int tg = lane >> 2;
    const int ti = lane & 3;
#pragma unroll
    for (int ma = 0; ma < 4; ma++) {
#pragma unroll
        for (int na = 0; na < 4; na++) {
#pragma unroll
            for (int rr = 0; rr < 2; rr++) {
                int m = m0 + wm * 64 + ma * 16 + tg + rr * 8;
                int n = n0 + wn * 32 + na * 8 + 2 * ti;
                float c0 = acc[ma][na][rr * 2 + 0];
                float c1 = acc[ma][na][rr * 2 + 1];
                if (MODE == 0) {
                    float2 v2 = make_float2(c0, c1);
                    *(float2*)&C[(size_t)m * Dn + n] = v2;
                } else {
                    int b = m >> 11;
                    int t = m & 2047;
                    int h = n >> 6;
                    int d = n & 63;
                    float* outp = &C[(((size_t)(b * Hn + h)) * Tn + t) * DH + d];
                    if (MODE == 2) {
                        float cc = g_cos[t * (DH / 2) + (d >> 1)];
                        float ss = g_sin[t * (DH / 2) + (d >> 1)];
                        outp[0] = c0 * cc - c1 * ss;
                        outp[1] = c0 * ss + c1 * cc;
                    } else {
                        float2 v2 = make_float2(c0, c1);
                        *(float2*)outp = v2;
                    }
                }
            }
        }
    }
}

// ---------------------------------------------------------------------------
// Tensor-core flash attention (bf16x3 emulation), causal.
// BQ=128 (8 warps x m16), BKV=64, dh=64.
// S acc fragments -> softmax in registers -> P repacked as A-fragments.
// ---------------------------------------------------------------------------
#define LDV 72   // bf16 row stride: 144B -> ldmatrix conflict-free

__global__ void __launch_bounds__(256) attn_tc(float* __restrict__ Oatt) {
    __shared__ __align__(16) __nv_bfloat16 smA[64 * LDV];  // Kh (Q stage: Qh rows 0-63)
    __shared__ __align__(16) __nv_bfloat16 smB[64 * LDV];  // Kl (Qh rows 64-127)
    __shared__ __align__(16) __nv_bfloat16 smC[64 * LDV];  // Vh (Ql rows 0-63)
    __shared__ __align__(16) __nv_bfloat16 smD[64 * LDV];  // Vl (Ql rows 64-127)

    const int tid = threadIdx.x;
    const int w = tid >> 5;
    const int lane = tid & 31;
    const int tg = lane >> 2;
    const int ti = lane & 3;
    const int bx = blockIdx.x;
    const int h = blockIdx.y;
    const int b = blockIdx.z;
    const int q0 = bx * 128;

    const float* Qb = g_q + ((size_t)(b * Hn + h)) * Tn * DH;
    const float* Kb = g_k + ((size_t)(b * Hn + h)) * Tn * DH;
    const float* Vb = g_v + ((size_t)(b * Hn + h)) * Tn * DH;

    const unsigned a_base = (unsigned)__cvta_generic_to_shared(smA);
    const unsigned b_base = (unsigned)__cvta_generic_to_shared(smB);
    const unsigned c_base = (unsigned)__cvta_generic_to_shared(smC);
    const unsigned d_base = (unsigned)__cvta_generic_to_shared(smD);

    // ---- stage Q: fp32 -> hi/lo bf16 smem ----
#pragma unroll
    for (int it = 0; it < 8; it++) {
        int i = tid + it * 256;          // 0..2047
        int row = i >> 4;                // 0..127
        int c = (i & 15) * 4;
        float4 q4 = *(const float4*)&Qb[(size_t)(q0 + row) * DH + c];
        __nv_bfloat16* hp = (row < 64 ? smA : smB) + (row & 63) * LDV + c;
        __nv_bfloat16* lp = (row < 64 ? smC : smD) + (row & 63) * LDV + c;
        split_store(q4.x, q4.y, hp, lp);
        split_store(q4.z, q4.w, hp + 2, lp + 2);
    }
    __syncthreads();

    // ---- Q fragments (held in registers for the whole block) ----
    unsigned qh[4][4], ql[4][4];
    {
        const unsigned qh_b = (w < 4) ? a_base : b_base;
        const unsigned ql_b = (w < 4) ? c_base : d_base;
        const int ar = (w & 3) * 16 + (lane & 7) + ((lane >> 3) & 1) * 8;
#pragma unroll
        for (int ks = 0; ks < 4; ks++) {
            int ac = ks * 16 + (lane >> 4) * 8;
            unsigned off = (unsigned)((ar * LDV + ac) * 2);
            ldsm4(qh[ks], qh_b + off);
            ldsm4(ql[ks], ql_b + off);
        }
    }

    float o[8][4];
#pragma unroll
    for (int j = 0; j < 8; j++)
#pragma unroll
        for (int r = 0; r < 4; r++) o[j][r] = 0.0f;
    float m_i[2] = {-1.0e30f, -1.0e30f};
    float l_i[2] = {0.0f, 0.0f};

    const int jt_end = 2 * bx + 2;
    for (int jt = 0; jt < jt_end; jt++) {
        const int k0 = jt * 64;
        __syncthreads();   // previous tile compute done (first iter: Q frags read)
        // ---- load K/V tile, split hi/lo ----
#pragma unroll
        for (int it = 0; it < 4; it++) {
            int i = tid + it * 256;      // 0..1023
            int row = i >> 4;            // 0..63
            int c = (i & 15) * 4;
            float4 k4 = *(const float4*)&Kb[(size_t)(k0 + row) * DH + c];
            split_store(k4.x, k4.y, &smA[row * LDV + c],     &smB[row * LDV + c]);
            split_store(k4.z, k4.w, &smA[row * LDV + c + 2], &smB[row * LDV + c + 2]);
            float4 v4 = *(const float4*)&Vb[(size_t)(k0 + row) * DH + c];
            split_store(v4.x, v4.y, &smC[row * LDV + c],     &smD[row * LDV + c]);
            split_store(v4.z, v4.w, &smC[row * LDV + c + 2], &smD[row * LDV + c + 2]);
        }
        __syncthreads();

        const bool active = (k0 <= q0 + w * 16 + 15);
        if (active) {
            // ---- S = Q @ K^T ----
            float s[8][4];
#pragma unroll
            for (int j = 0; j < 8; j++)
#pragma unroll
                for (int r = 0; r < 4; r++) s[j][r] = 0.0f;

#pragma unroll
            for (int ks = 0; ks < 4; ks++) {
#pragma unroll
                for (int nb = 0; nb < 4; nb++) {
                    const int br = nb * 16 + (lane & 7) + (lane >> 4) * 8;
                    const int bc = ks * 16 + ((lane >> 3) & 1) * 8;
                    unsigned off = (unsigned)((br * LDV + bc) * 2);
                    unsigned kh[4], kl[4];
                    ldsm4(kh, a_base + off);
                    ldsm4(kl, b_base + off);
#pragma unroll
                    for (int jj = 0; jj < 2; jj++) {
                        const int j = 2 * nb + jj;
                        const int pr = jj * 2;
                        mma_bf16(s[j], qh[ks], kh[pr], kh[pr + 1]);
                        mma_bf16(s[j], qh[ks], kl[pr], kl[pr + 1]);
                        mma_bf16(s[j], ql[ks], kh[pr], kh[pr + 1]);
                    }
                }
            }

            // ---- scale + causal mask ----
            const bool domask = (jt >= 2 * bx);
#pragma unroll
            for (int j = 0; j < 8; j++) {
                const int colb = k0 + 8 * j + 2 * ti;
#pragma unroll
                for (int r = 0; r < 2; r++) {
                    const int rowg = q0 + w * 16 + tg + 8 * r;
                    float v0 = s[j][2 * r]     * 0.125f;
                    float v1 = s[j][2 * r + 1] * 0.125f;
                    if (domask && colb     > rowg) v0 = -3.0e38f;
                    if (domask && colb + 1 > rowg) v1 = -3.0e38f;
                    s[j][2 * r]     = v0;
                    s[j][2 * r + 1] = v1;
                }
            }

            // ---- online softmax (rows tg, tg+8; reduce over quad lanes) ----
#pragma unroll
            for (int r = 0; r < 2; r++) {
                float mx = -3.0e38f;
#pragma unroll
                for (int j = 0; j < 8; j++)
                    mx = fmaxf(mx, fmaxf(s[j][2 * r], s[j][2 * r + 1]));
                mx = fmaxf(mx, __shfl_xor_sync(0xffffffffu, mx, 1));
                mx = fmaxf(mx, __shfl_xor_sync(0xffffffffu, mx, 2));
                float mnew = fmaxf(m_i[r], mx);
                float alpha = __expf(m_i[r] - mnew);
                m_i[r] = mnew;
                float rs = 0.0f;
#pragma unroll
                for (int j = 0; j < 8; j++) {
                    float p0 = __expf(s[j][2 * r]     - mnew);
                    float p1 = __expf(s[j][2 * r + 1] - mnew);
                    s[j][2 * r] = p0;
                    s[j][2 * r + 1] = p1;
                    rs += p0 + p1;
                }
                rs += __shfl_xor_sync(0xffffffffu, rs, 1);
                rs += __shfl_xor_sync(0xffffffffu, rs, 2);
                l_i[r] = l_i[r] * alpha + rs;
#pragma unroll
                for (int j = 0; j < 8; j++) {
                    o[j][2 * r]     *= alpha;
                    o[j][2 * r + 1] *= alpha;
                }
            }

            // ---- repack P accumulators as A fragments (hi/lo) ----
            unsigned pah[4][4], pal[4][4];
#pragma unroll
            for (int u = 0; u < 4; u++) {
                split2(s[2 * u][0],     s[2 * u][1],     pah[u][0], pal[u][0]);
                split2(s[2 * u][2],     s[2 * u][3],     pah[u][1], pal[u][1]);
                split2(s[2 * u + 1][0], s[2 * u + 1][1], pah[u][2], pal[u][2]);
                split2(s[2 * u + 1][2], s[2 * u + 1][3], pah[u][3], pal[u][3]);
            }

            // ---- O += P @ V ----
#pragma unroll
            for (int u = 0; u < 4; u++) {
#pragma unroll
                for (int nb = 0; nb < 4; nb++) {
                    const int vr = u * 16 + (lane & 7) + ((lane >> 3) & 1) * 8;
                    const int vc = nb * 16 + (lane >> 4) * 8;
                    unsigned off = (unsigned)((vr * LDV + vc) * 2);
                    unsigned vh[4], vl[4];
                    ldsm4t(vh, c_base + off);
                    ldsm4t(vl, d_base + off);
#pragma unroll
                    for (int jj = 0; jj < 2; jj++) {
                        const int j = 2 * nb + jj;
                        const int pr = jj * 2;
                        mma_bf16(o[j], pah[u], vh[pr], vh[pr + 1]);
                        mma_bf16(o[j], pah[u], vl[pr], vl[pr + 1]);
                        mma_bf16(o[j], pal[u], vh[pr], vh[pr + 1]);
                    }
                }
            }
        }
    }

    // ---- epilogue: normalize + store to [B, T, H*dh] ----
#pragma unroll
    for (int r = 0; r < 2; r++) {
        float inv = 1.0f / l_i[r];
        int rowg = q0 + w * 16 + tg + 8 * r;
        float* orow = Oatt + ((size_t)b * Tn + rowg) * Dn + h * DH;
#pragma unroll
        for (int j = 0; j < 8; j++) {
            float2 v = make_float2(o[j][2 * r] * inv, o[j][2 * r + 1] * inv);
            *(float2*)&orow[8 * j + 2 * ti] = v;
        }
    }
}

// ---------------------------------------------------------------------------
// launch
// ---------------------------------------------------------------------------
extern "C" void kernel_launch(void* const* d_in, const int* in_sizes, int n_in,
                              void* d_out, int out_size) {
    const float* x  = (const float*)d_in[0];
    const float* wq = (const float*)d_in[1];
    const float* wk = (const float*)d_in[2];
    const float* wv = (const float*)d_in[3];
    const float* wo = (const float*)d_in[4];
    float* out = (float*)d_out;

    float *pq, *pk, *pv, *patt;
    cudaGetSymbolAddress((void**)&pq, g_q);
    cudaGetSymbolAddress((void**)&pk, g_k);
    cudaGetSymbolAddress((void**)&pv, g_v);
    cudaGetSymbolAddress((void**)&patt, g_att);

    rope_table_kernel<<<(Tn * (DH / 2) + 255) / 256, 256>>>();

    dim3 gg(Dn / 128, MT / 128);
    gemm_tc<2><<<gg, 256>>>(x, wq, pq);
    gemm_tc<2><<<gg, 256>>>(x, wk, pk);
    gemm_tc<1><<<gg, 256>>>(x, wv, pv);

    attn_tc<<<dim3(Tn / 128, Hn, Bc), 256>>>(patt);

    gemm_tc<0><<<gg, 256>>>(patt, wo, out);
}

// round 6
// speedup vs baseline: 3.3360x; 1.1312x over previous
#include <cuda_runtime.h>
#include <cuda_bf16.h>
#include <cstdint>
#include <math.h>

// Problem constants
#define Bc 2
#define Hn 16
#define Tn 2048
#define Dn 1024
#define DH 64
#define MT (Bc * Tn)   // 4096 rows

// ---------------------------------------------------------------------------
// Scratch (device globals; no cudaMalloc allowed). All operands pre-split
// into bf16 (hi, lo) pairs: x = hi + lo with |lo| ~ 2^-9 |x|.
// ---------------------------------------------------------------------------
__device__ __nv_bfloat16 g_xh[MT * Dn], g_xl[MT * Dn];
__device__ __nv_bfloat16 g_wqh[Dn * Dn], g_wql[Dn * Dn];
__device__ __nv_bfloat16 g_wkh[Dn * Dn], g_wkl[Dn * Dn];
__device__ __nv_bfloat16 g_wvh[Dn * Dn], g_wvl[Dn * Dn];
__device__ __nv_bfloat16 g_woh[Dn * Dn], g_wol[Dn * Dn];
__device__ __nv_bfloat16 g_qh[MT * Dn], g_ql[MT * Dn];   // [B,H,T,dh]
__device__ __nv_bfloat16 g_kh[MT * Dn], g_kl[MT * Dn];
__device__ __nv_bfloat16 g_vh[MT * Dn], g_vl[MT * Dn];
__device__ __nv_bfloat16 g_oh[MT * Dn], g_ol[MT * Dn];   // [B,T,D]
__device__ float g_cos[Tn * (DH / 2)];
__device__ float g_sin[Tn * (DH / 2)];

// ---------------------------------------------------------------------------
// RoPE cos/sin table (fp64 trig on fp32-rounded angle; fast-math-proof)
// ---------------------------------------------------------------------------
__global__ void rope_table_kernel() {
    int idx = blockIdx.x * blockDim.x + threadIdx.x;
    if (idx >= Tn * (DH / 2)) return;
    int t = idx / (DH / 2);
    int i = idx % (DH / 2);
    float freq = (float)(1.0 / pow(10000.0, (double)(2 * i) / (double)DH));
    float ang = (float)t * freq;
    g_cos[idx] = (float)cos((double)ang);
    g_sin[idx] = (float)sin((double)ang);
}

// ---------------------------------------------------------------------------
// fp32 -> (hi, lo) bf16 split kernel
// ---------------------------------------------------------------------------
__global__ void split_kernel(const float* __restrict__ in,
                             __nv_bfloat16* __restrict__ oh,
                             __nv_bfloat16* __restrict__ ol, int n4) {
    int i = blockIdx.x * blockDim.x + threadIdx.x;
    if (i >= n4) return;
    float4 v = ((const float4*)in)[i];
    __nv_bfloat162 h0, h1, l0, l1;
    h0.x = __float2bfloat16(v.x);
    h0.y = __float2bfloat16(v.y);
    h1.x = __float2bfloat16(v.z);
    h1.y = __float2bfloat16(v.w);
    l0.x = __float2bfloat16(v.x - __bfloat162float(h0.x));
    l0.y = __float2bfloat16(v.y - __bfloat162float(h0.y));
    l1.x = __float2bfloat16(v.z - __bfloat162float(h1.x));
    l1.y = __float2bfloat16(v.w - __bfloat162float(h1.y));
    ((__nv_bfloat162*)oh)[2 * i] = h0;
    ((__nv_bfloat162*)oh)[2 * i + 1] = h1;
    ((__nv_bfloat162*)ol)[2 * i] = l0;
    ((__nv_bfloat162*)ol)[2 * i + 1] = l1;
}

// ---------------------------------------------------------------------------
// PTX helpers
// ---------------------------------------------------------------------------
__device__ __forceinline__ void mma_bf16(float* c, const unsigned* a,
                                         unsigned b0, unsigned b1) {
    asm volatile(
        "mma.sync.aligned.m16n8k16.row.col.f32.bf16.bf16.f32 "
        "{%0,%1,%2,%3}, {%4,%5,%6,%7}, {%8,%9}, {%0,%1,%2,%3};\n"
        : "+f"(c[0]), "+f"(c[1]), "+f"(c[2]), "+f"(c[3])
        : "r"(a[0]), "r"(a[1]), "r"(a[2]), "r"(a[3]), "r"(b0), "r"(b1));
}
__device__ __forceinline__ void ldsm4(unsigned* r, unsigned addr) {
    asm volatile("ldmatrix.sync.aligned.m8n8.x4.shared.b16 {%0,%1,%2,%3}, [%4];\n"
                 : "=r"(r[0]), "=r"(r[1]), "=r"(r[2]), "=r"(r[3]) : "r"(addr));
}
__device__ __forceinline__ void ldsm4t(unsigned* r, unsigned addr) {
    asm volatile("ldmatrix.sync.aligned.m8n8.x4.trans.shared.b16 {%0,%1,%2,%3}, [%4];\n"
                 : "=r"(r[0]), "=r"(r[1]), "=r"(r[2]), "=r"(r[3]) : "r"(addr));
}
__device__ __forceinline__ void cp16(unsigned s, const void* g) {
    asm volatile("cp.async.cg.shared.global [%0], [%1], 16;" :: "r"(s), "l"(g));
}
#define CP_COMMIT() asm volatile("cp.async.commit_group;" ::: "memory")
#define CP_WAIT1()  asm volatile("cp.async.wait_group 1;" ::: "memory")
#define CP_WAIT0()  asm volatile("cp.async.wait_group 0;" ::: "memory")

__device__ __forceinline__ void split2(float x, float y, unsigned& h, unsigned& l) {
    __nv_bfloat162 hh, ll;
    hh.x = __float2bfloat16(x);
    hh.y = __float2bfloat16(y);
    ll.x = __float2bfloat16(x - __bfloat162float(hh.x));
    ll.y = __float2bfloat16(y - __bfloat162float(hh.y));
    h = *(unsigned*)&hh;
    l = *(unsigned*)&ll;
}

// ---------------------------------------------------------------------------
// Pre-split tensor-core NT GEMM: C = A @ W^T with A = Ah+Al, W = Wh+Wl (bf16).
// M=4096, N=K=1024. Block 128x128, BK=32, 8 warps (64x32 warp tile).
// cp.async double-buffered. bf16x3: acc += Ah*Wh + Ah*Wl + Al*Wh.
// MODE 0: fp32 flat store. MODE 1: split-store [B,H,T,dh]. MODE 2: + RoPE.
// ---------------------------------------------------------------------------
#define LDK 40                 // smem row stride (bf16)
#define GARR (128 * LDK * 2)   // 10240 B per array
#define GSTG (4 * GARR)        // 40960 B per stage
#define GSMEM (2 * GSTG)       // 81920 B

template <int MODE>
__global__ void __launch_bounds__(256) gemm_bs(
    const __nv_bfloat16* __restrict__ Ah, const __nv_bfloat16* __restrict__ Al,
    const __nv_bfloat16* __restrict__ Wh, const __nv_bfloat16* __restrict__ Wl,
    float* __restrict__ C, __nv_bfloat16* __restrict__ Ch, __nv_bfloat16* __restrict__ Cl) {
    extern __shared__ __align__(16) char smg[];
    const unsigned smem_u = (unsigned)__cvta_generic_to_shared(smg);
    const int tid = threadIdx.x;
    const int warp = tid >> 5;
    const int lane = tid & 31;
    const int m0 = blockIdx.y * 128;
    const int n0 = blockIdx.x * 128;
    const int wm = warp >> 2;
    const int wn = warp & 3;

    // per-thread load slots: 8 cp.async of 16B per stage
    const __nv_bfloat16* gsrc[4] = {Ah, Al, Wh, Wl};

    float acc[4][4][4];
#pragma unroll
    for (int i = 0; i < 4; i++)
#pragma unroll
        for (int j = 0; j < 4; j++)
#pragma unroll
            for (int r = 0; r < 4; r++) acc[i][j][r] = 0.0f;

    // issue stage for k-chunk `ch` into buffer `buf`
    auto issue = [&](int ch, int buf) {
        const int k0 = ch * 32;
        const unsigned sb = smem_u + buf * GSTG;
#pragma unroll
        for (int t = 0; t < 8; t++) {
            const int arr = t >> 1;                 // 0 Ah, 1 Al, 2 Wh, 3 Wl
            const int chunk = tid + (t & 1) * 256;  // 0..511
            const int row = chunk >> 2;             // 0..127
            const int c8 = (chunk & 3) * 8;
            const int base = (arr < 2 ? m0 : n0);
            const __nv_bfloat16* gp = gsrc[arr] + (size_t)(base + row) * Dn + k0 + c8;
            cp16(sb + arr * GARR + (unsigned)((row * LDK + c8) * 2), gp);
        }
        CP_COMMIT();
    };

    issue(0, 0);

    for (int ch = 0; ch < Dn / 32; ch++) {
        const int buf = ch & 1;
        const bool more = (ch + 1 < Dn / 32);
        if (more) issue(ch + 1, buf ^ 1);
        if (more) CP_WAIT1(); else CP_WAIT0();
        __syncthreads();

        const unsigned sb = smem_u + buf * GSTG;
        const unsigned ah_b = sb;
        const unsigned al_b = sb + GARR;
        const unsigned bh_b = sb + 2 * GARR;
        const unsigned bl_b = sb + 3 * GARR;

#pragma unroll
        for (int s = 0; s < 2; s++) {
            const int ks = s * 16;
            unsigned ah[4][4], al[4][4], bh[2][4], bl[2][4];
            const int ar = wm * 64 + (lane & 7) + ((lane >> 3) & 1) * 8;
            const int ac = ks + (lane >> 4) * 8;
#pragma unroll
            for (int ma = 0; ma < 4; ma++) {
                unsigned off = (unsigned)(((ar + ma * 16) * LDK + ac) * 2);
                ldsm4(ah[ma], ah_b + off);
                ldsm4(al[ma], al_b + off);
            }
            const int br = wn * 32 + (lane & 7) + (lane >> 4) * 8;
            const int bc = ks + ((lane >> 3) & 1) * 8;
#pragma unroll
            for (int nb = 0; nb < 2; nb++) {
                unsigned off = (unsigned)(((br + nb * 16) * LDK + bc) * 2);
                ldsm4(bh[nb], bh_b + off);
                ldsm4(bl[nb], bl_b + off);
            }
#pragma unroll
            for (int ma = 0; ma < 4; ma++)
#pragma unroll
                for (int na = 0; na < 4; na++) {
                    const int nb = na >> 1, pr = (na & 1) * 2;
                    mma_bf16(acc[ma][na], ah[ma], bh[nb][pr], bh[nb][pr + 1]);
                    mma_bf16(acc[ma][na], ah[ma], bl[nb][pr], bl[nb][pr + 1]);
                    mma_bf16(acc[ma][na], al[ma], bh[nb][pr], bh[nb][pr + 1]);
                }
        }
        __syncthreads();
    }

    // epilogue
    const int tg = lane >> 2;
    const int ti = lane & 3;
#pragma unroll
    for (int ma = 0; ma < 4; ma++) {
#pragma unroll
        for (int na = 0; na < 4; na++) {
#pragma unroll
            for (int rr = 0; rr < 2; rr++) {
                int m = m0 + wm * 64 + ma * 16 + tg + rr * 8;
                int n = n0 + wn * 32 + na * 8 + 2 * ti;
                float c0 = acc[ma][na][rr * 2 + 0];
                float c1 = acc[ma][na][rr * 2 + 1];
                if (MODE == 0) {
                    float2 v2 = make_float2(c0, c1);
                    *(float2*)&C[(size_t)m * Dn + n] = v2;
                } else {
                    int b = m >> 11;
                    int t = m & 2047;
                    int h = n >> 6;
                    int d = n & 63;
                    if (MODE == 2) {
                        float cc = g_cos[t * (DH / 2) + (d >> 1)];
                        float ss = g_sin[t * (DH / 2) + (d >> 1)];
                        float r0 = c0 * cc - c1 * ss;
                        float r1 = c0 * ss + c1 * cc;
                        c0 = r0;
                        c1 = r1;
                    }
                    unsigned hreg, lreg;
                    split2(c0, c1, hreg, lreg);
                    size_t idx = (((size_t)(b * Hn + h)) * Tn + t) * DH + d;
                    *(unsigned*)&Ch[idx] = hreg;
                    *(unsigned*)&Cl[idx] = lreg;
                }
            }
        }
    }
}

// ---------------------------------------------------------------------------
// Tensor-core flash attention (bf16x3), causal, pre-split bf16 inputs.
// BQ=128 (8 warps x m16), BKV=64, dh=64. cp.async double-buffered K/V.
// Output: hi/lo bf16 [B,T,D] for the output projection GEMM.
// ---------------------------------------------------------------------------
#define LDV 72
#define AARR (64 * LDV * 2)   // 9216 B per array
#define ASTG (4 * AARR)       // 36864 B per stage
#define ASMEM (2 * ASTG)      // 73728 B

__global__ void __launch_bounds__(256) attn_bs() {
    extern __shared__ __align__(16) char sma[];
    const unsigned smem_u = (unsigned)__cvta_generic_to_shared(sma);
    const int tid = threadIdx.x;
    const int w = tid >> 5;
    const int lane = tid & 31;
    const int tg = lane >> 2;
    const int ti = lane & 3;
    const int qt = gridDim.x - 1 - blockIdx.x;   // heavy tiles first
    const int h = blockIdx.y;
    const int b = blockIdx.z;
    const int q0 = qt * 128;

    const size_t hoff = ((size_t)(b * Hn + h)) * Tn * DH;
    const __nv_bfloat16* Qh = g_qh + hoff;
    const __nv_bfloat16* Ql = g_ql + hoff;
    const __nv_bfloat16* srcKV[4] = {g_kh + hoff, g_kl + hoff, g_vh + hoff, g_vl + hoff};

    // ---- stage Q (plain copies into stage 0) ----
#pragma unroll
    for (int t = 0; t < 8; t++) {
        int chunk = tid + t * 256;        // 0..2047
        int row = (chunk >> 3) & 127;
        int c8 = (chunk & 7) * 8;
        bool hi = chunk < 1024;
        const __nv_bfloat16* src = (hi ? Qh : Ql) + (size_t)(q0 + row) * DH + c8;
        int arr = (hi ? 0 : 2) + (row >> 6);   // 0:A 1:B 2:C 3:D
        uint4 v = *(const uint4*)src;
        *(uint4*)(sma + arr * AARR + ((row & 63) * LDV + c8) * 2) = v;
    }
    __syncthreads();

    // ---- Q fragments ----
    unsigned qh[4][4], ql[4][4];
    {
        const unsigned qh_b = smem_u + ((w < 4) ? 0 : AARR);
        const unsigned ql_b = smem_u + ((w < 4) ? 2 * AARR : 3 * AARR);
        const int ar = (w & 3) * 16 + (lane & 7) + ((lane >> 3) & 1) * 8;
#pragma unroll
        for (int ks = 0; ks < 4; ks++) {
            int ac = ks * 16 + (lane >> 4) * 8;
            unsigned off = (unsigned)((ar * LDV + ac) * 2);
            ldsm4(qh[ks], qh_b + off);
            ldsm4(ql[ks], ql_b + off);
        }
    }
    __syncthreads();   // all warps done reading Q before stage-0 reuse

    float o[8][4];
#pragma unroll
    for (int j = 0; j < 8; j++)
#pragma unroll
        for (int r = 0; r < 4; r++) o[j][r] = 0.0f;
    float m_i[2] = {-1.0e30f, -1.0e30f};
    float l_i[2] = {0.0f, 0.0f};

    const int jt_end = 2 * qt + 2;

    // issue K/V tile jt into stage buf
    auto issue = [&](int jt, int buf) {
        const int k0 = jt * 64;
        const unsigned sb = smem_u + buf * ASTG;
#pragma unroll
        for (int t = 0; t < 8; t++) {
            const int arr = t >> 1;                 // kh, kl, vh, vl
            const int chunk = tid + (t & 1) * 256;  // 0..511
            const int row = chunk >> 3;             // 0..63
            const int c8 = (chunk & 7) * 8;
            const __nv_bfloat16* gp = srcKV[arr] + (size_t)(k0 + row) * DH + c8;
            cp16(sb + arr * AARR + (unsigned)((row * LDV + c8) * 2), gp);
        }
        CP_COMMIT();
    };

    issue(0, 0);

    for (int jt = 0; jt < jt_end; jt++) {
        const int k0 = jt * 64;
        const int buf = jt & 1;
        const bool more = (jt + 1 < jt_end);
        if (more) issue(jt + 1, buf ^ 1);
        if (more) CP_WAIT1(); else CP_WAIT0();
        __syncthreads();

        const unsigned kh_b = smem_u + buf * ASTG;
        const unsigned kl_b = kh_b + AARR;
        const unsigned vh_b = kh_b + 2 * AARR;
        const unsigned vl_b = kh_b + 3 * AARR;

        const bool active = (k0 <= q0 + w * 16 + 15);
        if (active) {
            float s[8][4];
#pragma unroll
            for (int j = 0; j < 8; j++)
#pragma unroll
                for (int r = 0; r < 4; r++) s[j][r] = 0.0f;

#pragma unroll
            for (int ks = 0; ks < 4; ks++) {
#pragma unroll
                for (int nb = 0; nb < 4; nb++) {
                    const int br = nb * 16 + (lane & 7) + (lane >> 4) * 8;
                    const int bc = ks * 16 + ((lane >> 3) & 1) * 8;
                    unsigned off = (unsigned)((br * LDV + bc) * 2);
                    unsigned kh[4], kl[4];
                    ldsm4(kh, kh_b + off);
                    ldsm4(kl, kl_b + off);
#pragma unroll
                    for (int jj = 0; jj < 2; jj++) {
                        const int j = 2 * nb + jj;
                        const int pr = jj * 2;
                        mma_bf16(s[j], qh[ks], kh[pr], kh[pr + 1]);
                        mma_bf16(s[j], qh[ks], kl[pr], kl[pr + 1]);
                        mma_bf16(s[j], ql[ks], kh[pr], kh[pr + 1]);
                    }
                }
            }

            const bool domask = (jt >= 2 * qt);
#pragma unroll
            for (int j = 0; j < 8; j++) {
                const int colb = k0 + 8 * j + 2 * ti;
#pragma unroll
                for (int r = 0; r < 2; r++) {
                    const int rowg = q0 + w * 16 + tg + 8 * r;
                    float v0 = s[j][2 * r]     * 0.125f;
                    float v1 = s[j][2 * r + 1] * 0.125f;
                    if (domask && colb     > rowg) v0 = -3.0e38f;
                    if (domask && colb + 1 > rowg) v1 = -3.0e38f;
                    s[j][2 * r]     = v0;
                    s[j][2 * r + 1] = v1;
                }
            }

#pragma unroll
            for (int r = 0; r < 2; r++) {
                float mx = -3.0e38f;
#pragma unroll
                for (int j = 0; j < 8; j++)
                    mx = fmaxf(mx, fmaxf(s[j][2 * r], s[j][2 * r + 1]));
                mx = fmaxf(mx, __shfl_xor_sync(0xffffffffu, mx, 1));
                mx = fmaxf(mx, __shfl_xor_sync(0xffffffffu, mx, 2));
                float mnew = fmaxf(m_i[r], mx);
                float alpha = __expf(m_i[r] - mnew);
                m_i[r] = mnew;
                float rs = 0.0f;
#pragma unroll
                for (int j = 0; j < 8; j++) {
                    float p0 = __expf(s[j][2 * r]     - mnew);
                    float p1 = __expf(s[j][2 * r + 1] - mnew);
                    s[j][2 * r] = p0;
                    s[j][2 * r + 1] = p1;
                    rs += p0 + p1;
                }
                rs += __shfl_xor_sync(0xffffffffu, rs, 1);
                rs += __shfl_xor_sync(0xffffffffu, rs, 2);
                l_i[r] = l_i[r] * alpha + rs;
#pragma unroll
                for (int j = 0; j < 8; j++) {
                    o[j][2 * r]     *= alpha;
                    o[j][2 * r + 1] *= alpha;
                }
            }

            unsigned pah[4][4], pal[4][4];
#pragma unroll
            for (int u = 0; u < 4; u++) {
                split2(s[2 * u][0],     s[2 * u][1],     pah[u][0], pal[u][0]);
                split2(s[2 * u][2],     s[2 * u][3],     pah[u][1], pal[u][1]);
                split2(s[2 * u + 1][0], s[2 * u + 1][1], pah[u][2], pal[u][2]);
                split2(s[2 * u + 1][2], s[2 * u + 1][3], pah[u][3], pal[u][3]);
            }

#pragma unroll
            for (int u = 0; u < 4; u++) {
#pragma unroll
                for (int nb = 0; nb < 4; nb++) {
                    const int vr = u * 16 + (lane & 7) + ((lane >> 3) & 1) * 8;
                    const int vc = nb * 16 + (lane >> 4) * 8;
                    unsigned off = (unsigned)((vr * LDV + vc) * 2);
                    unsigned vh[4], vl[4];
                    ldsm4t(vh, vh_b + off);
                    ldsm4t(vl, vl_b + off);
#pragma unroll
                    for (int jj = 0; jj < 2; jj++) {
                        const int j = 2 * nb + jj;
                        const int pr = jj * 2;
                        mma_bf16(o[j], pah[u], vh[pr], vh[pr + 1]);
                        mma_bf16(o[j], pah[u], vl[pr], vl[pr + 1]);
                        mma_bf16(o[j], pal[u], vh[pr], vh[pr + 1]);
                    }
                }
            }
        }
        __syncthreads();
    }

    // ---- epilogue: normalize, split to hi/lo bf16 [B,T,D] ----
#pragma unroll
    for (int r = 0; r < 2; r++) {
        float inv = 1.0f / l_i[r];
        int rowg = q0 + w * 16 + tg + 8 * r;
        size_t base = ((size_t)b * Tn + rowg) * Dn + h * DH;
#pragma unroll
        for (int j = 0; j < 8; j++) {
            unsigned hreg, lreg;
            split2(o[j][2 * r] * inv, o[j][2 * r + 1] * inv, hreg, lreg);
            *(unsigned*)&g_oh[base + 8 * j + 2 * ti] = hreg;
            *(unsigned*)&g_ol[base + 8 * j + 2 * ti] = lreg;
        }
    }
}

// ---------------------------------------------------------------------------
// launch
// ---------------------------------------------------------------------------
extern "C" void kernel_launch(void* const* d_in, const int* in_sizes, int n_in,
                              void* d_out, int out_size) {
    const float* x  = (const float*)d_in[0];
    const float* wq = (const float*)d_in[1];
    const float* wk = (const float*)d_in[2];
    const float* wv = (const float*)d_in[3];
    const float* wo = (const float*)d_in[4];
    float* out = (float*)d_out;

    __nv_bfloat16 *xh, *xl, *wqh, *wql, *wkh, *wkl, *wvh, *wvl, *woh, *wol;
    __nv_bfloat16 *qh, *ql, *kh, *kl, *vh, *vl, *oh, *ol;
    cudaGetSymbolAddress((void**)&xh, g_xh);   cudaGetSymbolAddress((void**)&xl, g_xl);
    cudaGetSymbolAddress((void**)&wqh, g_wqh); cudaGetSymbolAddress((void**)&wql, g_wql);
    cudaGetSymbolAddress((void**)&wkh, g_wkh); cudaGetSymbolAddress((void**)&wkl, g_wkl);
    cudaGetSymbolAddress((void**)&wvh, g_wvh); cudaGetSymbolAddress((void**)&wvl, g_wvl);
    cudaGetSymbolAddress((void**)&woh, g_woh); cudaGetSymbolAddress((void**)&wol, g_wol);
    cudaGetSymbolAddress((void**)&qh, g_qh);   cudaGetSymbolAddress((void**)&ql, g_ql);
    cudaGetSymbolAddress((void**)&kh, g_kh);   cudaGetSymbolAddress((void**)&kl, g_kl);
    cudaGetSymbolAddress((void**)&vh, g_vh);   cudaGetSymbolAddress((void**)&vl, g_vl);
    cudaGetSymbolAddress((void**)&oh, g_oh);   cudaGetSymbolAddress((void**)&ol, g_ol);

    cudaFuncSetAttribute(gemm_bs<0>, cudaFuncAttributeMaxDynamicSharedMemorySize, GSMEM);
    cudaFuncSetAttribute(gemm_bs<1>, cudaFuncAttributeMaxDynamicSharedMemorySize, GSMEM);
    cudaFuncSetAttribute(gemm_bs<2>, cudaFuncAttributeMaxDynamicSharedMemorySize, GSMEM);
    cudaFuncSetAttribute(attn_bs, cudaFuncAttributeMaxDynamicSharedMemorySize, ASMEM);

    rope_table_kernel<<<(Tn * (DH / 2) + 255) / 256, 256>>>();

    // pre-split inputs
    split_kernel<<<(MT * Dn / 4 + 255) / 256, 256>>>(x, xh, xl, MT * Dn / 4);
    split_kernel<<<(Dn * Dn / 4 + 255) / 256, 256>>>(wq, wqh, wql, Dn * Dn / 4);
    split_kernel<<<(Dn * Dn / 4 + 255) / 256, 256>>>(wk, wkh, wkl, Dn * Dn / 4);
    split_kernel<<<(Dn * Dn / 4 + 255) / 256, 256>>>(wv, wvh, wvl, Dn * Dn / 4);
    split_kernel<<<(Dn * Dn / 4 + 255) / 256, 256>>>(wo, woh, wol, Dn * Dn / 4);

    dim3 gg(Dn / 128, MT / 128);
    gemm_bs<2><<<gg, 256, GSMEM>>>(xh, xl, wqh, wql, nullptr, qh, ql);
    gemm_bs<2><<<gg, 256, GSMEM>>>(xh, xl, wkh, wkl, nullptr, kh, kl);
    gemm_bs<1><<<gg, 256, GSMEM>>>(xh, xl, wvh, wvl, nullptr, vh, vl);

    attn_bs<<<dim3(Tn / 128, Hn, Bc), 256, ASMEM>>>();

    gemm_bs<0><<<gg, 256, GSMEM>>>(oh, ol, woh, wol, out, nullptr, nullptr);
}